// round 13
// baseline (speedup 1.0000x reference)
#include <cuda_runtime.h>
#include <cstdint>

// ---------------------------------------------------------------------------
// CausalTrajectoryPrediction: 64 per-node MLPs, B=1024, H=512, M=64, N=64.
//   h1 = relu(x_masked @ W1^T); r1 = relu(h1 @ W2^T)
//   h3 = relu(r1 @ W3[:, :64]^T + x_own * W3[:, 64+n] + b3)
//   out = relu(h3 @ W4 + b4)
// One CTA per (node n, 128-row batch tile), fully fused in SMEM, fp32 with
// packed fma.rn.f32x2. This revision: back to the R11 shape (128 thr, 8x8
// tile) + cp.async weight staging (4B scatter building the swizzled k-major
// tile) to free registers and make weight-load latency fully asynchronous.
// ---------------------------------------------------------------------------

#define THREADS 128
#define LDA 68   // padded row stride (floats), 16B aligned, bank-skewed

typedef unsigned long long ull;

__device__ __forceinline__ ull pk2(float lo, float hi) {
    ull r; asm("mov.b64 %0, {%1, %2};" : "=l"(r) : "f"(lo), "f"(hi)); return r;
}
__device__ __forceinline__ float2 upk2(ull v) {
    float2 r; asm("mov.b64 {%0, %1}, %2;" : "=f"(r.x), "=f"(r.y) : "l"(v)); return r;
}
__device__ __forceinline__ void fma2(ull& d, ull a, ull b) {
    asm("fma.rn.f32x2 %0, %1, %2, %0;" : "+l"(d) : "l"(a), "l"(b));
}

#define CP_COMMIT() asm volatile("cp.async.commit_group;" ::: "memory")
#define CP_WAIT0()  asm volatile("cp.async.wait_group 0;" ::: "memory")
#define CP_WAIT1()  asm volatile("cp.async.wait_group 1;" ::: "memory")

__device__ __forceinline__ void cp4(uint32_t dst, const float* src) {
    asm volatile("cp.async.ca.shared.global [%0], [%1], 4;"
                 :: "r"(dst), "l"(src) : "memory");
}

// ---- 64x64 weight tile async staging ---------------------------------------
// Physical layout (same as before): element (k, c) ->
//   W[k*64 + 4*(((c>>2) ^ (k>>2)) & 15) + (c&3)]
// src: 64 rows (one per output col c), contiguous along k: src[c*rowstride+k].
// 4-byte cp.async scatter: each of 128 threads copies 32 elements.
__device__ __forceinline__ void stage_tile(uint32_t dstW,
                                           const float* __restrict__ src,
                                           int rowstride) {
    int f  = threadIdx.x & 15;    // k-group: k = 4f + j
    int c0 = threadIdx.x >> 4;    // 0..7
#pragma unroll
    for (int p = 0; p < 8; ++p) {
        int c = c0 + 8 * p;
        int g = ((c >> 2) ^ f) & 15;
        const float* s = src + (size_t)c * rowstride + 4 * f;
        uint32_t d = dstW + (uint32_t)(((4 * f) * 64 + (g << 2) + (c & 3)) * 4);
#pragma unroll
        for (int j = 0; j < 4; ++j)
            cp4(d + (uint32_t)j * 256u, s + j);   // k=4f+j -> +64 floats
    }
}

// ---- 128x64x64 GEMM microkernel --------------------------------------------
// Thread (rt, ct): rows {rt + 16i, i=0..7}, cols {4ct..4ct+3} U {32+4ct..+3}.
__device__ __forceinline__ void gemm64(ull acc[8][4],
                                       const float* __restrict__ A,
                                       const float* __restrict__ W,
                                       int rt, int ct) {
    const float* Ab = A + rt * LDA;
#pragma unroll 4
    for (int k4 = 0; k4 < 64; k4 += 4) {
        float4 av[8];
#pragma unroll
        for (int i = 0; i < 8; ++i)
            av[i] = *(const float4*)(Ab + i * (16 * LDA) + k4);
        int s  = k4 >> 2;
        int g0 = (((ct    ) ^ s) & 15) << 2;
        int g1 = (((ct + 8) ^ s) & 15) << 2;
#pragma unroll
        for (int j = 0; j < 4; ++j) {
            const float* Wk = W + (k4 + j) * 64;
            ulonglong2 b01 = *(const ulonglong2*)(Wk + g0);
            ulonglong2 b23 = *(const ulonglong2*)(Wk + g1);
#pragma unroll
            for (int i = 0; i < 8; ++i) {
                float a = (j == 0) ? av[i].x : (j == 1) ? av[i].y
                         : (j == 2) ? av[i].z : av[i].w;
                ull p = pk2(a, a);
                fma2(acc[i][0], p, b01.x);
                fma2(acc[i][1], p, b01.y);
                fma2(acc[i][2], p, b23.x);
                fma2(acc[i][3], p, b23.y);
            }
        }
    }
}

__global__ void __launch_bounds__(THREADS, 2)
ctp_kernel(const float* __restrict__ x,  const float* __restrict__ W1,
           const float* __restrict__ W2, const float* __restrict__ W3,
           const float* __restrict__ b3, const float* __restrict__ W4,
           const float* __restrict__ b4, float* __restrict__ out) {
    extern __shared__ float sm[];
    float* Asm = sm;                 // 128 x 68 = 8704 (x tile, later r1)
    float* Hsm = Asm + 8704;         // 128 x 68 = 8704 (h1 chunk)
    float* Wa  = Hsm + 8704;         // 4096 (swizzled weight tile A)
    float* Wb  = Wa  + 4096;         // 4096 (swizzled weight tile B)
    float* W4s = Wb  + 4096;         // 512
    float* w3o = W4s + 512;          // 2 x 64 (own-input col, double buffer)
    float* b3s = w3o + 128;          // 2 x 64 (bias chunk, double buffer)
    float* xow = b3s + 128;          // 128 (x[:, n])

    const int n       = blockIdx.y;
    const int rowbase = blockIdx.x * 128;
    const int tid     = threadIdx.x;
    const int rt      = tid >> 3;    // 0..15 -> rows rt + 16i
    const int ct      = tid & 7;     // 0..7  -> cols 4ct..4ct+3 and +32

    const float* W1n = W1 + (size_t)n * 512 * 64;
    const float* W2n = W2 + (size_t)n * 64 * 512;
    const float* W3n = W3 + (size_t)n * 512 * 128;

    const uint32_t WaU  = (uint32_t)__cvta_generic_to_shared(Wa);
    const uint32_t WbU  = (uint32_t)__cvta_generic_to_shared(Wb);
    const uint32_t w3oU = (uint32_t)__cvta_generic_to_shared(w3o);
    const uint32_t b3sU = (uint32_t)__cvta_generic_to_shared(b3s);

    // ---- Kick off async weight staging for W1[0], W2[0] -------------------
    stage_tile(WaU, W1n, 64);  CP_COMMIT();
    stage_tile(WbU, W2n, 512); CP_COMMIT();

    // ---- Stage x tile (col n masked), W4, x_own ---------------------------
    {
        int f  = tid & 15;
        int r0 = tid >> 4;           // 0..7
#pragma unroll
        for (int p = 0; p < 16; ++p) {
            int row = r0 + p * 8;
            float4 v = *(const float4*)(x + (size_t)(rowbase + row) * 64 + f * 4);
            v.x = (4 * f + 0 == n) ? 0.0f : v.x;
            v.y = (4 * f + 1 == n) ? 0.0f : v.y;
            v.z = (4 * f + 2 == n) ? 0.0f : v.z;
            v.w = (4 * f + 3 == n) ? 0.0f : v.w;
            *(float4*)(Asm + row * LDA + f * 4) = v;
        }
    }
    for (int i = tid; i < 512; i += THREADS) W4s[i] = W4[(size_t)n * 512 + i];
    xow[tid] = x[(size_t)(rowbase + tid) * 64 + n];

    CP_WAIT1();            // W1[0] landed (thread-local)
    __syncthreads();       // all threads: Wa ready, Asm/W4s/xow visible

    // ---- Phase B: r1 = relu( relu(A @ W1^T) @ W2^T ), 2 syncs per chunk ---
    ull r1acc[8][4];
#pragma unroll
    for (int i = 0; i < 8; ++i)
#pragma unroll
        for (int q = 0; q < 4; ++q) r1acc[i][q] = 0ull;

    for (int hc = 0; hc < 8; ++hc) {
        ull acc[8][4];
#pragma unroll
        for (int i = 0; i < 8; ++i)
#pragma unroll
            for (int q = 0; q < 4; ++q) acc[i][q] = 0ull;
        gemm64(acc, Asm, Wa, rt, ct);        // h1 chunk = x @ W1[hc]^T

        // relu(h1) -> Hsm (gemm2(hc-1) finished at prev sync2)
#pragma unroll
        for (int i = 0; i < 8; ++i) {
            int row = rt + 16 * i;
            float2 v0 = upk2(acc[i][0]), v1 = upk2(acc[i][1]);
            float2 v2 = upk2(acc[i][2]), v3 = upk2(acc[i][3]);
            float4 lo = {fmaxf(v0.x, 0.f), fmaxf(v0.y, 0.f), fmaxf(v1.x, 0.f), fmaxf(v1.y, 0.f)};
            float4 hi = {fmaxf(v2.x, 0.f), fmaxf(v2.y, 0.f), fmaxf(v3.x, 0.f), fmaxf(v3.y, 0.f)};
            *(float4*)(Hsm + row * LDA + 4 * ct)      = lo;
            *(float4*)(Hsm + row * LDA + 32 + 4 * ct) = hi;
        }
        CP_WAIT0();        // W2[hc] -> Wb landed (thread-local)
        __syncthreads();   // sync1: Wb ready everywhere; Hsm visible; Wa free

        if (hc < 7) {
            stage_tile(WaU, W1n + (size_t)(hc + 1) * 4096, 64);   // W1[hc+1]
        } else {
            stage_tile(WaU, W3n, 128);                            // W3[0]
            if (tid < 64) {                                       // aux[0]
                cp4(w3oU + 4u * tid, W3n + (size_t)tid * 128 + 64 + n);
                cp4(b3sU + 4u * tid, b3 + (size_t)n * 512 + tid);
            }
        }
        CP_COMMIT();

        gemm64(r1acc, Hsm, Wb, rt, ct);      // r1 += h1 @ W2[hc]^T

        CP_WAIT0();        // Wa copy landed (thread-local)
        __syncthreads();   // sync2: Wa ready everywhere; Wb/Hsm free

        if (hc < 7) {
            stage_tile(WbU, W2n + (size_t)(hc + 1) * 64, 512);    // W2[hc+1]
            CP_COMMIT();
        }
    }

    // ---- Stage W3[1] + aux[1] into Wb; r1 = relu(r1acc) -> Asm ------------
    stage_tile(WbU, W3n + 8192, 128);
    if (tid < 64) {
        cp4(w3oU + 4u * (64 + tid), W3n + (size_t)(64 + tid) * 128 + 64 + n);
        cp4(b3sU + 4u * (64 + tid), b3 + (size_t)n * 512 + 64 + tid);
    }
    CP_COMMIT();

#pragma unroll
    for (int i = 0; i < 8; ++i) {
        int row = rt + 16 * i;
        float2 v0 = upk2(r1acc[i][0]), v1 = upk2(r1acc[i][1]);
        float2 v2 = upk2(r1acc[i][2]), v3 = upk2(r1acc[i][3]);
        float4 lo = {fmaxf(v0.x, 0.f), fmaxf(v0.y, 0.f), fmaxf(v1.x, 0.f), fmaxf(v1.y, 0.f)};
        float4 hi = {fmaxf(v2.x, 0.f), fmaxf(v2.y, 0.f), fmaxf(v3.x, 0.f), fmaxf(v3.y, 0.f)};
        *(float4*)(Asm + row * LDA + 4 * ct)      = lo;
        *(float4*)(Asm + row * LDA + 32 + 4 * ct) = hi;
    }
    __syncthreads();   // Asm(r1) visible; Wa(W3[0]) + aux[0] ready (waited above)

    // ---- Phase C: out = relu( relu(R @ W3a^T + x_own*w3own + b3) @ W4 + b4 )
    float partial[8] = {0.f, 0.f, 0.f, 0.f, 0.f, 0.f, 0.f, 0.f};
    const float b4n = b4[n];
    const int clo = 4 * ct, chi = 32 + 4 * ct;
    float xo[8];
#pragma unroll
    for (int i = 0; i < 8; ++i) xo[i] = xow[rt + 16 * i];

    for (int hc = 0; hc < 8; ++hc) {
        int buf = hc & 1;
        const float* Wc = buf ? Wb : Wa;
        const uint32_t WcU = buf ? WbU : WaU;
        const float* wo = w3o + buf * 64;
        const float* bb = b3s + buf * 64;

        ull acc[8][4];
#pragma unroll
        for (int i = 0; i < 8; ++i) {
            acc[i][0] = pk2(fmaf(xo[i], wo[clo],     bb[clo]),
                            fmaf(xo[i], wo[clo + 1], bb[clo + 1]));
            acc[i][1] = pk2(fmaf(xo[i], wo[clo + 2], bb[clo + 2]),
                            fmaf(xo[i], wo[clo + 3], bb[clo + 3]));
            acc[i][2] = pk2(fmaf(xo[i], wo[chi],     bb[chi]),
                            fmaf(xo[i], wo[chi + 1], bb[chi + 1]));
            acc[i][3] = pk2(fmaf(xo[i], wo[chi + 2], bb[chi + 2]),
                            fmaf(xo[i], wo[chi + 3], bb[chi + 3]));
        }
        gemm64(acc, Asm, Wc, rt, ct);

        // relu(h3 chunk) folded into the W4 dot product
#pragma unroll
        for (int i = 0; i < 8; ++i) {
#pragma unroll
            for (int q = 0; q < 4; ++q) {
                float2 v = upk2(acc[i][q]);
                int c = hc * 64 + ((q < 2) ? (clo + 2 * q) : (chi + 2 * (q - 2)));
                partial[i] = fmaf(fmaxf(v.x, 0.f), W4s[c],     partial[i]);
                partial[i] = fmaf(fmaxf(v.y, 0.f), W4s[c + 1], partial[i]);
            }
        }

        if (hc < 7) {
            CP_WAIT0();        // W3[hc+1] + aux[hc+1] landed (thread-local)
            __syncthreads();   // ready everywhere; current buf free
            if (hc + 2 < 8) {
                // Stage W3[hc+2] + aux[hc+2] into the buffer just freed.
                stage_tile(WcU, W3n + (size_t)(hc + 2) * 8192, 128);
                if (tid < 64) {
                    int h = (hc + 2) * 64 + tid;
                    uint32_t slot = (uint32_t)(((hc + 2) & 1) * 64 + tid) * 4u;
                    cp4(w3oU + slot, W3n + (size_t)h * 128 + 64 + n);
                    cp4(b3sU + slot, b3 + (size_t)n * 512 + h);
                }
                CP_COMMIT();
            }
        }
    }

    // ---- Reduce over the 8 ct lanes (lanes differ in tid bits 0..2) -------
#pragma unroll
    for (int i = 0; i < 8; ++i) {
        float v = partial[i];
        v += __shfl_xor_sync(0xffffffffu, v, 1);
        v += __shfl_xor_sync(0xffffffffu, v, 2);
        v += __shfl_xor_sync(0xffffffffu, v, 4);
        if (ct == 0)
            out[(size_t)(rowbase + rt + 16 * i) * 64 + n] = fmaxf(v + b4n, 0.0f);
    }
}

extern "C" void kernel_launch(void* const* d_in, const int* in_sizes, int n_in,
                              void* d_out, int out_size) {
    const float* x  = (const float*)d_in[0];
    const float* W1 = (const float*)d_in[1];
    const float* W2 = (const float*)d_in[2];
    const float* W3 = (const float*)d_in[3];
    const float* b3 = (const float*)d_in[4];
    const float* W4 = (const float*)d_in[5];
    const float* b4 = (const float*)d_in[6];
    float* out = (float*)d_out;

    const int smem_bytes = 26496 * (int)sizeof(float);  // 105984 B, 2 CTAs/SM
    cudaFuncSetAttribute(ctp_kernel,
                         cudaFuncAttributeMaxDynamicSharedMemorySize,
                         smem_bytes);

    dim3 grid(8, 64);   // 8 row tiles of 128 x 64 nodes
    ctp_kernel<<<grid, THREADS, smem_bytes>>>(x, W1, W2, W3, b3, W4, b4, out);
}